// round 1
// baseline (speedup 1.0000x reference)
#include <cuda_runtime.h>
#include <math.h>
#include <stdint.h>

#define HID 512
#define TI_A 32
#define HC   32
#define TI_B 16

// Fallback scratch for attn if d_out doesn't include the attn tensor.
__device__ float g_attn_scratch[64 * 128 * 128];

// ---------------------------------------------------------------------------
// Kernel A: scores = Q K^T / sqrt(H), row softmax, write attn[b][i][j].
// Block: (batch b, 32-row i tile). 256 threads = (ty 0..7) x (tx 0..31).
// Thread micro-tile: 4 i (ty*4..+3) x 4 j (tx, tx+32, tx+64, tx+96).
// j padded to 128 with zero K columns; masked with -inf before softmax.
// ---------------------------------------------------------------------------
__global__ __launch_bounds__(256) void qk_softmax_kernel(
    const float* __restrict__ q, const float* __restrict__ k,
    float* __restrict__ attn, int S)
{
    __shared__ float Qs[HC][TI_A + 1];   // [h][i]  stride 33 -> conflict-free
    __shared__ float Ks[HC][133];        // [h][j]  stride 133 -> conflict-free

    const int b   = blockIdx.x;
    const int i0  = blockIdx.y * TI_A;
    const int tid = threadIdx.x;
    const int tx  = tid & 31;
    const int ty  = tid >> 5;
    const int iy4 = ty * 4;

    const float* qb = q + (size_t)b * S * HID;
    const float* kb = k + (size_t)b * S * HID;

    float acc[4][4];
#pragma unroll
    for (int a = 0; a < 4; ++a)
#pragma unroll
        for (int c = 0; c < 4; ++c) acc[a][c] = 0.f;

    for (int h0 = 0; h0 < HID; h0 += HC) {
        // Load Q tile (32 rows x 32 h), transposed into Qs[h][i]
#pragma unroll
        for (int r = 0; r < 4; ++r) {
            int i = i0 + ty + 8 * r;
            Qs[tx][ty + 8 * r] = (i < S) ? qb[(size_t)i * HID + h0 + tx] : 0.f;
        }
        // Load K tile (128 rows x 32 h), rows >= S zero-filled
#pragma unroll
        for (int r = 0; r < 16; ++r) {
            int j = ty + 8 * r;
            Ks[tx][j] = (j < S) ? kb[(size_t)j * HID + h0 + tx] : 0.f;
        }
        __syncthreads();

#pragma unroll
        for (int h = 0; h < HC; ++h) {
            float q0 = Qs[h][iy4 + 0];
            float q1 = Qs[h][iy4 + 1];
            float q2 = Qs[h][iy4 + 2];
            float q3 = Qs[h][iy4 + 3];
            float k0 = Ks[h][tx];
            float k1 = Ks[h][tx + 32];
            float k2 = Ks[h][tx + 64];
            float k3 = Ks[h][tx + 96];
            acc[0][0] += q0 * k0; acc[0][1] += q0 * k1; acc[0][2] += q0 * k2; acc[0][3] += q0 * k3;
            acc[1][0] += q1 * k0; acc[1][1] += q1 * k1; acc[1][2] += q1 * k2; acc[1][3] += q1 * k3;
            acc[2][0] += q2 * k0; acc[2][1] += q2 * k1; acc[2][2] += q2 * k2; acc[2][3] += q2 * k3;
            acc[3][0] += q3 * k0; acc[3][1] += q3 * k1; acc[3][2] += q3 * k2; acc[3][3] += q3 * k3;
        }
        __syncthreads();
    }

    const float inv_t = 0.04419417382415922f;  // 1/sqrt(512)

    const bool v0 = (tx      ) < S;
    const bool v1 = (tx + 32 ) < S;
    const bool v2 = (tx + 64 ) < S;
    const bool v3 = (tx + 96 ) < S;

#pragma unroll
    for (int si = 0; si < 4; ++si) {
        int i = i0 + iy4 + si;
        float s0 = v0 ? acc[si][0] * inv_t : -INFINITY;
        float s1 = v1 ? acc[si][1] * inv_t : -INFINITY;
        float s2 = v2 ? acc[si][2] * inv_t : -INFINITY;
        float s3 = v3 ? acc[si][3] * inv_t : -INFINITY;

        float m = fmaxf(fmaxf(s0, s1), fmaxf(s2, s3));
#pragma unroll
        for (int o = 16; o > 0; o >>= 1)
            m = fmaxf(m, __shfl_xor_sync(0xffffffffu, m, o));

        float e0 = __expf(s0 - m);
        float e1 = __expf(s1 - m);
        float e2 = __expf(s2 - m);
        float e3 = __expf(s3 - m);

        float sum = e0 + e1 + e2 + e3;
#pragma unroll
        for (int o = 16; o > 0; o >>= 1)
            sum += __shfl_xor_sync(0xffffffffu, sum, o);

        float rinv = 1.0f / sum;
        if (i < S) {
            float* row = attn + ((size_t)b * S + i) * S;
            if (v0) row[tx]      = e0 * rinv;
            if (v1) row[tx + 32] = e1 * rinv;
            if (v2) row[tx + 64] = e2 * rinv;
            if (v3) row[tx + 96] = e3 * rinv;
        }
    }
}

// ---------------------------------------------------------------------------
// Kernel B: F = attn @ V, then region-weight combine:
//   i <  S-1: out = w2*F + (w1-w2)*C + (w0-w1)*a_ii*v_i + (w3-w2)*a_iq*v_q
//   i == S-1: out = w4*F + (w5-w4)*a_qq*v_q
// Block: (batch b, 16-row i tile). 128 threads; thread t owns h = 4t..4t+3.
// ---------------------------------------------------------------------------
__global__ __launch_bounds__(128) void out_kernel(
    const float* __restrict__ attn, const float* __restrict__ v,
    const float* __restrict__ aw, const int* __restrict__ Kp,
    float* __restrict__ out, int S)
{
    __shared__ float As[TI_B][104];

    const int b  = blockIdx.x;
    const int i0 = blockIdx.y * TI_B;
    const int t  = threadIdx.x;      // 0..127
    const int h  = t * 4;

    const float* vb = v + (size_t)b * S * HID;

    // Stage attn tile
    for (int idx = t; idx < TI_B * S; idx += 128) {
        int ii = idx / S;
        int jj = idx - ii * S;
        int i  = i0 + ii;
        As[ii][jj] = (i < S) ? attn[((size_t)b * S + i) * S + jj] : 0.f;
    }
    __syncthreads();

    float4 F[TI_B];
#pragma unroll
    for (int ii = 0; ii < TI_B; ++ii) F[ii] = make_float4(0.f, 0.f, 0.f, 0.f);

    // Main F accumulation with 1-deep V prefetch
    float4 v4 = *(const float4*)(vb + h);
    for (int j = 0; j < S; ++j) {
        float4 nv = make_float4(0.f, 0.f, 0.f, 0.f);
        if (j + 1 < S) nv = *(const float4*)(vb + (size_t)(j + 1) * HID + h);
#pragma unroll
        for (int ii = 0; ii < TI_B; ++ii) {
            float a = As[ii][j];
            F[ii].x += a * v4.x;
            F[ii].y += a * v4.y;
            F[ii].z += a * v4.z;
            F[ii].w += a * v4.w;
        }
        v4 = nv;
    }

    // Weight vectors at this h slice
    const float4 w0 = *(const float4*)(aw + 0 * HID + h);
    const float4 w1 = *(const float4*)(aw + 1 * HID + h);
    const float4 w2 = *(const float4*)(aw + 2 * HID + h);
    const float4 w3 = *(const float4*)(aw + 3 * HID + h);
    const float4 w4 = *(const float4*)(aw + 4 * HID + h);
    const float4 w5 = *(const float4*)(aw + 5 * HID + h);

    const float4 d12 = make_float4(w1.x - w2.x, w1.y - w2.y, w1.z - w2.z, w1.w - w2.w);
    const float4 d01 = make_float4(w0.x - w1.x, w0.y - w1.y, w0.z - w1.z, w0.w - w1.w);
    const float4 d32 = make_float4(w3.x - w2.x, w3.y - w2.y, w3.z - w2.z, w3.w - w2.w);
    const float4 d54 = make_float4(w5.x - w4.x, w5.y - w4.y, w5.z - w4.z, w5.w - w4.w);

    int Kv = 10;
    if (Kp != nullptr) {
        int kk = __ldg(Kp);
        if (kk > 0 && kk <= S) Kv = kk;
    }
    const int NKq = S - 1;
    const float4 vq = *(const float4*)(vb + (size_t)NKq * HID + h);

#pragma unroll 1
    for (int ii = 0; ii < TI_B; ++ii) {
        int i = i0 + ii;
        if (i >= S) break;
        float4 o;
        const float* arow = As[ii];

        if (i == NKq) {
            float aqq = arow[NKq];
            o.x = w4.x * F[ii].x + d54.x * aqq * vq.x;
            o.y = w4.y * F[ii].y + d54.y * aqq * vq.y;
            o.z = w4.z * F[ii].z + d54.z * aqq * vq.z;
            o.w = w4.w * F[ii].w + d54.w * aqq * vq.w;
        } else {
            int c0   = (i / Kv) * Kv;
            int cend = c0 + Kv;
            if (cend > NKq) cend = NKq;  // class region never includes the query col
            float4 C = make_float4(0.f, 0.f, 0.f, 0.f);
            for (int j = c0; j < cend; ++j) {
                float a = arow[j];
                float4 vv = *(const float4*)(vb + (size_t)j * HID + h);
                C.x += a * vv.x; C.y += a * vv.y; C.z += a * vv.z; C.w += a * vv.w;
            }
            float aii = arow[i];
            float aiq = arow[NKq];
            float4 vi = *(const float4*)(vb + (size_t)i * HID + h);

            o.x = w2.x * F[ii].x + d12.x * C.x + d01.x * aii * vi.x + d32.x * aiq * vq.x;
            o.y = w2.y * F[ii].y + d12.y * C.y + d01.y * aii * vi.y + d32.y * aiq * vq.y;
            o.z = w2.z * F[ii].z + d12.z * C.z + d01.z * aii * vi.z + d32.z * aiq * vq.z;
            o.w = w2.w * F[ii].w + d12.w * C.w + d01.w * aii * vi.w + d32.w * aiq * vq.w;
        }
        *(float4*)(out + ((size_t)b * S + i) * HID + h) = o;
    }
}

// ---------------------------------------------------------------------------
extern "C" void kernel_launch(void* const* d_in, const int* in_sizes, int n_in,
                              void* d_out, int out_size)
{
    const float* q  = (const float*)d_in[0];
    const float* k  = (const float*)d_in[1];
    const float* v  = (const float*)d_in[2];
    const float* aw = (const float*)d_in[3];
    const int*   Kp = (n_in >= 6) ? (const int*)d_in[5] : nullptr;

    long rows = (long)in_sizes[0] / HID;   // B * S
    int B = 64;
    int S = (int)(rows / B);
    if (S <= 0 || (long)B * S != rows) { B = 1; S = (int)rows; }

    float* out = (float*)d_out;
    long need_with_attn = (long)B * S * HID + (long)B * S * S;
    float* attn;
    if ((long)out_size >= need_with_attn) {
        attn = out + (long)B * S * HID;
    } else {
        void* p = nullptr;
        cudaGetSymbolAddress(&p, g_attn_scratch);
        attn = (float*)p;
    }

    dim3 gA(B, (S + TI_A - 1) / TI_A);
    qk_softmax_kernel<<<gA, 256>>>(q, k, attn, S);

    dim3 gB(B, (S + TI_B - 1) / TI_B);
    out_kernel<<<gB, 128>>>(attn, v, aw, Kp, out, S);
}

// round 3
// speedup vs baseline: 1.4195x; 1.4195x over previous
#include <cuda_runtime.h>
#include <math.h>
#include <stdint.h>

#define HID 512
#define TI_A 32
#define TI_B 16

typedef unsigned long long ull;

__device__ __forceinline__ ull fma2(ull a, ull b, ull c) {
    ull d;
    asm("fma.rn.f32x2 %0, %1, %2, %3;" : "=l"(d) : "l"(a), "l"(b), "l"(c));
    return d;
}
__device__ __forceinline__ ull pack2(float lo, float hi) {
    ull d;
    asm("mov.b64 %0, {%1, %2};" : "=l"(d) : "f"(lo), "f"(hi));
    return d;
}
__device__ __forceinline__ float2 unpack2(ull a) {
    float lo, hi;
    asm("mov.b64 {%0, %1}, %2;" : "=f"(lo), "=f"(hi) : "l"(a));
    return make_float2(lo, hi);
}

// Fallback scratch for attn if d_out doesn't include the attn tensor.
__device__ float g_attn_scratch[64 * 128 * 128];

// ---------------------------------------------------------------------------
// Kernel A: scores = Q K^T / sqrt(H), row softmax, write attn[b][i][j].
// Block: (batch b, 32-row i tile). 256 threads = (ty 0..7) x (tx 0..31).
// Thread micro-tile: 4 i x 4 j. h packed in pairs -> fma.rn.f32x2.
// ---------------------------------------------------------------------------
__global__ __launch_bounds__(256) void qk_softmax_kernel(
    const float* __restrict__ q, const float* __restrict__ k,
    float* __restrict__ attn, int S)
{
    __shared__ ull Qs2[16][33];    // [h2][i]
    __shared__ ull Ks2[16][129];   // [h2][j]

    const int b   = blockIdx.x;
    const int i0  = blockIdx.y * TI_A;
    const int tid = threadIdx.x;
    const int tx  = tid & 31;
    const int ty  = tid >> 5;
    const int iy4 = ty * 4;
    const int h2l  = tx & 15;      // which h-pair this thread loads
    const int lr   = ty * 2 + (tx >> 4);   // 0..15 row selector for loads

    const float* qb = q + (size_t)b * S * HID;
    const float* kb = k + (size_t)b * S * HID;

    ull acc2[4][4];
#pragma unroll
    for (int a = 0; a < 4; ++a)
#pragma unroll
        for (int c = 0; c < 4; ++c) acc2[a][c] = 0ull;   // (0.0f, 0.0f)

    for (int h0 = 0; h0 < HID; h0 += 32) {
        // Q tile: 32 i x 16 h-pairs
#pragma unroll
        for (int r = 0; r < 2; ++r) {
            int il = lr + 16 * r;
            int i  = i0 + il;
            float2 val = (i < S) ? *(const float2*)(qb + (size_t)i * HID + h0 + h2l * 2)
                                 : make_float2(0.f, 0.f);
            *(float2*)&Qs2[h2l][il] = val;
        }
        // K tile: 128 j x 16 h-pairs (j >= S zero-filled)
#pragma unroll
        for (int r = 0; r < 8; ++r) {
            int j = lr + 16 * r;
            float2 val = (j < S) ? *(const float2*)(kb + (size_t)j * HID + h0 + h2l * 2)
                                 : make_float2(0.f, 0.f);
            *(float2*)&Ks2[h2l][j] = val;
        }
        __syncthreads();

#pragma unroll
        for (int h2 = 0; h2 < 16; ++h2) {
            ull q0 = Qs2[h2][iy4 + 0];
            ull q1 = Qs2[h2][iy4 + 1];
            ull q2 = Qs2[h2][iy4 + 2];
            ull q3 = Qs2[h2][iy4 + 3];
            ull k0 = Ks2[h2][tx];
            ull k1 = Ks2[h2][tx + 32];
            ull k2 = Ks2[h2][tx + 64];
            ull k3 = Ks2[h2][tx + 96];
            acc2[0][0] = fma2(q0, k0, acc2[0][0]);
            acc2[0][1] = fma2(q0, k1, acc2[0][1]);
            acc2[0][2] = fma2(q0, k2, acc2[0][2]);
            acc2[0][3] = fma2(q0, k3, acc2[0][3]);
            acc2[1][0] = fma2(q1, k0, acc2[1][0]);
            acc2[1][1] = fma2(q1, k1, acc2[1][1]);
            acc2[1][2] = fma2(q1, k2, acc2[1][2]);
            acc2[1][3] = fma2(q1, k3, acc2[1][3]);
            acc2[2][0] = fma2(q2, k0, acc2[2][0]);
            acc2[2][1] = fma2(q2, k1, acc2[2][1]);
            acc2[2][2] = fma2(q2, k2, acc2[2][2]);
            acc2[2][3] = fma2(q2, k3, acc2[2][3]);
            acc2[3][0] = fma2(q3, k0, acc2[3][0]);
            acc2[3][1] = fma2(q3, k1, acc2[3][1]);
            acc2[3][2] = fma2(q3, k2, acc2[3][2]);
            acc2[3][3] = fma2(q3, k3, acc2[3][3]);
        }
        __syncthreads();
    }

    const float inv_t = 0.04419417382415922f;  // 1/sqrt(512)

    const bool v0 = (tx      ) < S;
    const bool v1 = (tx + 32 ) < S;
    const bool v2 = (tx + 64 ) < S;
    const bool v3 = (tx + 96 ) < S;

#pragma unroll
    for (int si = 0; si < 4; ++si) {
        int i = i0 + iy4 + si;
        float2 a0 = unpack2(acc2[si][0]);
        float2 a1 = unpack2(acc2[si][1]);
        float2 a2 = unpack2(acc2[si][2]);
        float2 a3 = unpack2(acc2[si][3]);
        float s0 = v0 ? (a0.x + a0.y) * inv_t : -INFINITY;
        float s1 = v1 ? (a1.x + a1.y) * inv_t : -INFINITY;
        float s2 = v2 ? (a2.x + a2.y) * inv_t : -INFINITY;
        float s3 = v3 ? (a3.x + a3.y) * inv_t : -INFINITY;

        float m = fmaxf(fmaxf(s0, s1), fmaxf(s2, s3));
#pragma unroll
        for (int o = 16; o > 0; o >>= 1)
            m = fmaxf(m, __shfl_xor_sync(0xffffffffu, m, o));

        float e0 = __expf(s0 - m);
        float e1 = __expf(s1 - m);
        float e2 = __expf(s2 - m);
        float e3 = __expf(s3 - m);

        float sum = e0 + e1 + e2 + e3;
#pragma unroll
        for (int o = 16; o > 0; o >>= 1)
            sum += __shfl_xor_sync(0xffffffffu, sum, o);

        float rinv = 1.0f / sum;
        if (i < S) {
            float* row = attn + ((size_t)b * S + i) * S;
            if (v0) row[tx]      = e0 * rinv;
            if (v1) row[tx + 32] = e1 * rinv;
            if (v2) row[tx + 64] = e2 * rinv;
            if (v3) row[tx + 96] = e3 * rinv;
        }
    }
}

// ---------------------------------------------------------------------------
// Kernel B: F = attn @ V, then region-weight combine:
//   i <  S-1: out = w2*F + (w1-w2)*C + (w0-w1)*a_ii*v_i + (w3-w2)*a_iq*v_q
//   i == S-1: out = w4*F + (w5-w4)*a_qq*v_q
// Block: (batch b, 16-row i tile). 256 threads = (tx 0..127 h-lane, ts 0..1
// row-half). attn staged in smem as duplicated pairs (a,a) so one LDS.64
// feeds two fma.f32x2 (4 h) per (row, j).
// ---------------------------------------------------------------------------
__global__ __launch_bounds__(256, 3) void out_kernel(
    const float* __restrict__ attn, const float* __restrict__ v,
    const float* __restrict__ aw, const int* __restrict__ Kp,
    float* __restrict__ out, int S)
{
    __shared__ float2 Asd[TI_B][102];

    const int b  = blockIdx.x;
    const int i0 = blockIdx.y * TI_B;
    const int t  = threadIdx.x;      // 0..255
    const int tx = t & 127;
    const int ts = t >> 7;           // 0/1: rows [ts*8, ts*8+8)
    const int h  = tx * 4;

    const float* vb = v + (size_t)b * S * HID;

    // Stage attn tile, each value duplicated into a float2
    for (int idx = t; idx < TI_B * S; idx += 256) {
        int ii = idx / S;
        int jj = idx - ii * S;
        int i  = i0 + ii;
        float a = (i < S) ? attn[((size_t)b * S + i) * S + jj] : 0.f;
        Asd[ii][jj] = make_float2(a, a);
    }
    __syncthreads();

    ull F2[8][2];
#pragma unroll
    for (int ii = 0; ii < 8; ++ii) { F2[ii][0] = 0ull; F2[ii][1] = 0ull; }

    const int r0 = ts * 8;

    // F accumulation with 2-deep V prefetch
    float4 vc = *(const float4*)(vb + h);
    float4 vn = (S > 1) ? *(const float4*)(vb + (size_t)HID + h)
                        : make_float4(0.f, 0.f, 0.f, 0.f);
    for (int j = 0; j < S; ++j) {
        float4 vf = make_float4(0.f, 0.f, 0.f, 0.f);
        if (j + 2 < S) vf = *(const float4*)(vb + (size_t)(j + 2) * HID + h);
        ull vlo = pack2(vc.x, vc.y);
        ull vhi = pack2(vc.z, vc.w);
#pragma unroll
        for (int ii = 0; ii < 8; ++ii) {
            ull a2 = *(const ull*)&Asd[r0 + ii][j];
            F2[ii][0] = fma2(a2, vlo, F2[ii][0]);
            F2[ii][1] = fma2(a2, vhi, F2[ii][1]);
        }
        vc = vn; vn = vf;
    }

    // Weight vectors at this h slice
    const float4 w0 = *(const float4*)(aw + 0 * HID + h);
    const float4 w1 = *(const float4*)(aw + 1 * HID + h);
    const float4 w2 = *(const float4*)(aw + 2 * HID + h);
    const float4 w3 = *(const float4*)(aw + 3 * HID + h);
    const float4 w4 = *(const float4*)(aw + 4 * HID + h);
    const float4 w5 = *(const float4*)(aw + 5 * HID + h);

    const float4 d12 = make_float4(w1.x - w2.x, w1.y - w2.y, w1.z - w2.z, w1.w - w2.w);
    const float4 d01 = make_float4(w0.x - w1.x, w0.y - w1.y, w0.z - w1.z, w0.w - w1.w);
    const float4 d32 = make_float4(w3.x - w2.x, w3.y - w2.y, w3.z - w2.z, w3.w - w2.w);
    const float4 d54 = make_float4(w5.x - w4.x, w5.y - w4.y, w5.z - w4.z, w5.w - w4.w);

    int Kv = 10;
    if (Kp != nullptr) {
        int kk = __ldg(Kp);
        if (kk > 0 && kk <= S) Kv = kk;
    }
    const int NKq = S - 1;
    const float4 vq = *(const float4*)(vb + (size_t)NKq * HID + h);

#pragma unroll 1
    for (int ii = 0; ii < 8; ++ii) {
        int i = i0 + r0 + ii;
        if (i >= S) break;
        float2 flo = unpack2(F2[ii][0]);
        float2 fhi = unpack2(F2[ii][1]);
        float4 F = make_float4(flo.x, flo.y, fhi.x, fhi.y);
        float4 o;

        if (i == NKq) {
            float aqq = Asd[r0 + ii][NKq].x;
            o.x = w4.x * F.x + d54.x * aqq * vq.x;
            o.y = w4.y * F.y + d54.y * aqq * vq.y;
            o.z = w4.z * F.z + d54.z * aqq * vq.z;
            o.w = w4.w * F.w + d54.w * aqq * vq.w;
        } else {
            int c0   = (i / Kv) * Kv;
            int cend = c0 + Kv;
            if (cend > NKq) cend = NKq;  // class region never includes the query col
            float4 C = make_float4(0.f, 0.f, 0.f, 0.f);
            for (int j = c0; j < cend; ++j) {
                float a = Asd[r0 + ii][j].x;
                float4 vv = *(const float4*)(vb + (size_t)j * HID + h);
                C.x += a * vv.x; C.y += a * vv.y; C.z += a * vv.z; C.w += a * vv.w;
            }
            float aii = Asd[r0 + ii][i].x;    // global column i (attn[i][i])
            float aiq = Asd[r0 + ii][NKq].x;
            float4 vi = *(const float4*)(vb + (size_t)i * HID + h);

            o.x = w2.x * F.x + d12.x * C.x + d01.x * aii * vi.x + d32.x * aiq * vq.x;
            o.y = w2.y * F.y + d12.y * C.y + d01.y * aii * vi.y + d32.y * aiq * vq.y;
            o.z = w2.z * F.z + d12.z * C.z + d01.z * aii * vi.z + d32.z * aiq * vq.z;
            o.w = w2.w * F.w + d12.w * C.w + d01.w * aii * vi.w + d32.w * aiq * vq.w;
        }
        *(float4*)(out + ((size_t)b * S + i) * HID + h) = o;
    }
}

// ---------------------------------------------------------------------------
extern "C" void kernel_launch(void* const* d_in, const int* in_sizes, int n_in,
                              void* d_out, int out_size)
{
    const float* q  = (const float*)d_in[0];
    const float* k  = (const float*)d_in[1];
    const float* v  = (const float*)d_in[2];
    const float* aw = (const float*)d_in[3];
    const int*   Kp = (n_in >= 6) ? (const int*)d_in[5] : nullptr;

    long rows = (long)in_sizes[0] / HID;   // B * S
    int B = 64;
    int S = (int)(rows / B);
    if (S <= 0 || (long)B * S != rows) { B = 1; S = (int)rows; }

    float* out = (float*)d_out;
    long need_with_attn = (long)B * S * HID + (long)B * S * S;
    float* attn;
    if ((long)out_size >= need_with_attn) {
        attn = out + (long)B * S * HID;
    } else {
        void* p = nullptr;
        cudaGetSymbolAddress(&p, g_attn_scratch);
        attn = (float*)p;
    }

    dim3 gA(B, (S + TI_A - 1) / TI_A);
    qk_softmax_kernel<<<gA, 256>>>(q, k, attn, S);

    dim3 gB(B, (S + TI_B - 1) / TI_B);
    out_kernel<<<gB, 256>>>(attn, v, aw, Kp, out, S);
}

// round 4
// speedup vs baseline: 1.4201x; 1.0004x over previous
#include <cuda_runtime.h>
#include <math.h>
#include <stdint.h>

#define HID 512
#define TI_A 32
#define TI_B 16

typedef unsigned long long ull;

__device__ __forceinline__ ull fma2(ull a, ull b, ull c) {
    ull d;
    asm("fma.rn.f32x2 %0, %1, %2, %3;" : "=l"(d) : "l"(a), "l"(b), "l"(c));
    return d;
}
__device__ __forceinline__ float2 unpack2(ull a) {
    float lo, hi;
    asm("mov.b64 {%0, %1}, %2;" : "=f"(lo), "=f"(hi) : "l"(a));
    return make_float2(lo, hi);
}

// Fallback scratch for attn if d_out doesn't include the attn tensor.
__device__ float g_attn_scratch[64 * 128 * 128];

// ---------------------------------------------------------------------------
// Kernel A: scores = Q K^T / sqrt(H), row softmax, write attn[b][i][j].
// Block: (batch b, 32-row i tile). 256 threads = (ty 0..7) x (tx 0..31).
// Thread micro-tile: 4 i x 4 j with j = {2tx, 2tx+1, 2tx+64, 2tx+65} so both
// K pairs are adjacent -> LDS.128. h packed in pairs -> fma.rn.f32x2.
// h-chunk = 64 floats (32 pairs).
// ---------------------------------------------------------------------------
__global__ __launch_bounds__(256) void qk_softmax_kernel(
    const float* __restrict__ q, const float* __restrict__ k,
    float* __restrict__ attn, int S)
{
    __shared__ ull Qs2[32][34];    // [h2][i]   even stride -> 16B alignment
    __shared__ ull Ks2[32][130];   // [h2][j]

    const int b   = blockIdx.x;
    const int i0  = blockIdx.y * TI_A;
    const int tid = threadIdx.x;
    const int tx  = tid & 31;
    const int ty  = tid >> 5;
    const int iy4 = ty * 4;

    const float* qb = q + (size_t)b * S * HID;
    const float* kb = k + (size_t)b * S * HID;

    ull acc2[4][4];
#pragma unroll
    for (int a = 0; a < 4; ++a)
#pragma unroll
        for (int c = 0; c < 4; ++c) acc2[a][c] = 0ull;   // (0.0f, 0.0f)

    for (int h0 = 0; h0 < HID; h0 += 64) {
        // Q tile: 32 i x 32 h-pairs. thread: h2 = tx, i = ty + 8r
#pragma unroll
        for (int r = 0; r < 4; ++r) {
            int il = ty + 8 * r;
            int i  = i0 + il;
            float2 val = (i < S) ? *(const float2*)(qb + (size_t)i * HID + h0 + tx * 2)
                                 : make_float2(0.f, 0.f);
            *(float2*)&Qs2[tx][il] = val;
        }
        // K tile: 128 j x 32 h-pairs (j >= S zero-filled)
#pragma unroll
        for (int r = 0; r < 16; ++r) {
            int j = ty + 8 * r;
            float2 val = (j < S) ? *(const float2*)(kb + (size_t)j * HID + h0 + tx * 2)
                                 : make_float2(0.f, 0.f);
            *(float2*)&Ks2[tx][j] = val;
        }
        __syncthreads();

#pragma unroll
        for (int h2 = 0; h2 < 32; ++h2) {
            ulonglong2 qa = *(const ulonglong2*)&Qs2[h2][iy4];      // q0,q1
            ulonglong2 qc = *(const ulonglong2*)&Qs2[h2][iy4 + 2];  // q2,q3
            ulonglong2 ka = *(const ulonglong2*)&Ks2[h2][2 * tx];        // j=2tx,2tx+1
            ulonglong2 kc = *(const ulonglong2*)&Ks2[h2][2 * tx + 64];   // j=2tx+64,+65
            acc2[0][0] = fma2(qa.x, ka.x, acc2[0][0]);
            acc2[0][1] = fma2(qa.x, ka.y, acc2[0][1]);
            acc2[0][2] = fma2(qa.x, kc.x, acc2[0][2]);
            acc2[0][3] = fma2(qa.x, kc.y, acc2[0][3]);
            acc2[1][0] = fma2(qa.y, ka.x, acc2[1][0]);
            acc2[1][1] = fma2(qa.y, ka.y, acc2[1][1]);
            acc2[1][2] = fma2(qa.y, kc.x, acc2[1][2]);
            acc2[1][3] = fma2(qa.y, kc.y, acc2[1][3]);
            acc2[2][0] = fma2(qc.x, ka.x, acc2[2][0]);
            acc2[2][1] = fma2(qc.x, ka.y, acc2[2][1]);
            acc2[2][2] = fma2(qc.x, kc.x, acc2[2][2]);
            acc2[2][3] = fma2(qc.x, kc.y, acc2[2][3]);
            acc2[3][0] = fma2(qc.y, ka.x, acc2[3][0]);
            acc2[3][1] = fma2(qc.y, ka.y, acc2[3][1]);
            acc2[3][2] = fma2(qc.y, kc.x, acc2[3][2]);
            acc2[3][3] = fma2(qc.y, kc.y, acc2[3][3]);
        }
        __syncthreads();
    }

    const float inv_t = 0.04419417382415922f;  // 1/sqrt(512)

    const int c0 = 2 * tx;
    const int c2 = 2 * tx + 64;
    const bool v0 = (c0    ) < S;
    const bool v1 = (c0 + 1) < S;
    const bool v2 = (c2    ) < S;
    const bool v3 = (c2 + 1) < S;

#pragma unroll
    for (int si = 0; si < 4; ++si) {
        int i = i0 + iy4 + si;
        float2 a0 = unpack2(acc2[si][0]);
        float2 a1 = unpack2(acc2[si][1]);
        float2 a2 = unpack2(acc2[si][2]);
        float2 a3 = unpack2(acc2[si][3]);
        float s0 = v0 ? (a0.x + a0.y) * inv_t : -INFINITY;
        float s1 = v1 ? (a1.x + a1.y) * inv_t : -INFINITY;
        float s2 = v2 ? (a2.x + a2.y) * inv_t : -INFINITY;
        float s3 = v3 ? (a3.x + a3.y) * inv_t : -INFINITY;

        float m = fmaxf(fmaxf(s0, s1), fmaxf(s2, s3));
#pragma unroll
        for (int o = 16; o > 0; o >>= 1)
            m = fmaxf(m, __shfl_xor_sync(0xffffffffu, m, o));

        float e0 = __expf(s0 - m);
        float e1 = __expf(s1 - m);
        float e2 = __expf(s2 - m);
        float e3 = __expf(s3 - m);

        float sum = e0 + e1 + e2 + e3;
#pragma unroll
        for (int o = 16; o > 0; o >>= 1)
            sum += __shfl_xor_sync(0xffffffffu, sum, o);

        float rinv = 1.0f / sum;
        if (i < S) {
            float* row = attn + ((size_t)b * S + i) * S;
            if (v0) row[c0]     = e0 * rinv;
            if (v1) row[c0 + 1] = e1 * rinv;
            if (v2) row[c2]     = e2 * rinv;
            if (v3) row[c2 + 1] = e3 * rinv;
        }
    }
}

// ---------------------------------------------------------------------------
// Kernel B: F = attn @ V, then region-weight combine:
//   i <  S-1: out = w2*F + (w1-w2)*C + (w0-w1)*a_ii*v_i + (w3-w2)*a_iq*v_q
//   i == S-1: out = w4*F + (w5-w4)*a_qq*v_q
// Block: (batch b, 16-row i tile). 256 threads = (tx 0..127 h-lane, ts 0..1
// row-half). attn staged in smem as duplicated pairs (a,a); one broadcast
// LDS.128 = (a_j,a_j,a_j1,a_j1) feeds 4 fma.f32x2 covering 2 j x 4 h.
// ---------------------------------------------------------------------------
__global__ __launch_bounds__(256, 3) void out_kernel(
    const float* __restrict__ attn, const float* __restrict__ v,
    const float* __restrict__ aw, const int* __restrict__ Kp,
    float* __restrict__ out, int S)
{
    __shared__ float2 Asd[TI_B][102];

    const int b  = blockIdx.x;
    const int i0 = blockIdx.y * TI_B;
    const int t  = threadIdx.x;      // 0..255
    const int tx = t & 127;
    const int ts = t >> 7;           // 0/1: rows [ts*8, ts*8+8)
    const int h  = tx * 4;

    const float* vb = v + (size_t)b * S * HID;

    // Stage attn tile, each value duplicated into a float2 (pad one col)
    for (int idx = t; idx < TI_B * 102; idx += 256) {
        int ii = idx / 102;
        int jj = idx - ii * 102;
        int i  = i0 + ii;
        float a = (i < S && jj < S) ? attn[((size_t)b * S + i) * S + jj] : 0.f;
        Asd[ii][jj] = make_float2(a, a);
    }
    __syncthreads();

    ull F2[8][2];
#pragma unroll
    for (int ii = 0; ii < 8; ++ii) { F2[ii][0] = 0ull; F2[ii][1] = 0ull; }

    const int r0 = ts * 8;

    // F accumulation, j unrolled by 2, V prefetched one pair ahead
    ulonglong2 vj  = *(const ulonglong2*)(vb + h);
    ulonglong2 vj1 = (S > 1) ? *(const ulonglong2*)(vb + (size_t)HID + h)
                             : make_ulonglong2(0ull, 0ull);
    int j = 0;
    for (; j + 1 < S; j += 2) {
        ulonglong2 nvj  = make_ulonglong2(0ull, 0ull);
        ulonglong2 nvj1 = make_ulonglong2(0ull, 0ull);
        if (j + 3 < S) {
            nvj  = *(const ulonglong2*)(vb + (size_t)(j + 2) * HID + h);
            nvj1 = *(const ulonglong2*)(vb + (size_t)(j + 3) * HID + h);
        } else if (j + 2 < S) {
            nvj  = *(const ulonglong2*)(vb + (size_t)(j + 2) * HID + h);
        }
#pragma unroll
        for (int ii = 0; ii < 8; ++ii) {
            ulonglong2 a2 = *(const ulonglong2*)&Asd[r0 + ii][j];
            F2[ii][0] = fma2(a2.x, vj.x,  F2[ii][0]);
            F2[ii][1] = fma2(a2.x, vj.y,  F2[ii][1]);
            F2[ii][0] = fma2(a2.y, vj1.x, F2[ii][0]);
            F2[ii][1] = fma2(a2.y, vj1.y, F2[ii][1]);
        }
        vj = nvj; vj1 = nvj1;
    }
    if (j < S) {  // odd tail (vj holds V[S-1])
#pragma unroll
        for (int ii = 0; ii < 8; ++ii) {
            ull a2 = *(const ull*)&Asd[r0 + ii][j];
            F2[ii][0] = fma2(a2, vj.x, F2[ii][0]);
            F2[ii][1] = fma2(a2, vj.y, F2[ii][1]);
        }
    }

    // Weight vectors at this h slice
    const float4 w0 = *(const float4*)(aw + 0 * HID + h);
    const float4 w1 = *(const float4*)(aw + 1 * HID + h);
    const float4 w2 = *(const float4*)(aw + 2 * HID + h);
    const float4 w3 = *(const float4*)(aw + 3 * HID + h);
    const float4 w4 = *(const float4*)(aw + 4 * HID + h);
    const float4 w5 = *(const float4*)(aw + 5 * HID + h);

    const float4 d12 = make_float4(w1.x - w2.x, w1.y - w2.y, w1.z - w2.z, w1.w - w2.w);
    const float4 d01 = make_float4(w0.x - w1.x, w0.y - w1.y, w0.z - w1.z, w0.w - w1.w);
    const float4 d32 = make_float4(w3.x - w2.x, w3.y - w2.y, w3.z - w2.z, w3.w - w2.w);
    const float4 d54 = make_float4(w5.x - w4.x, w5.y - w4.y, w5.z - w4.z, w5.w - w4.w);

    int Kv = 10;
    if (Kp != nullptr) {
        int kk = __ldg(Kp);
        if (kk > 0 && kk <= S) Kv = kk;
    }
    const int NKq = S - 1;
    const float4 vq = *(const float4*)(vb + (size_t)NKq * HID + h);

#pragma unroll 1
    for (int ii = 0; ii < 8; ++ii) {
        int i = i0 + r0 + ii;
        if (i >= S) break;
        float2 flo = unpack2(F2[ii][0]);
        float2 fhi = unpack2(F2[ii][1]);
        float4 F = make_float4(flo.x, flo.y, fhi.x, fhi.y);
        float4 o;

        if (i == NKq) {
            float aqq = Asd[r0 + ii][NKq].x;
            o.x = w4.x * F.x + d54.x * aqq * vq.x;
            o.y = w4.y * F.y + d54.y * aqq * vq.y;
            o.z = w4.z * F.z + d54.z * aqq * vq.z;
            o.w = w4.w * F.w + d54.w * aqq * vq.w;
        } else {
            int c0   = (i / Kv) * Kv;
            int cend = c0 + Kv;
            if (cend > NKq) cend = NKq;  // class region never includes the query col
            float4 C = make_float4(0.f, 0.f, 0.f, 0.f);
            for (int jj = c0; jj < cend; ++jj) {
                float a = Asd[r0 + ii][jj].x;
                float4 vv = *(const float4*)(vb + (size_t)jj * HID + h);
                C.x += a * vv.x; C.y += a * vv.y; C.z += a * vv.z; C.w += a * vv.w;
            }
            float aii = Asd[r0 + ii][i].x;    // attn[i][i]
            float aiq = Asd[r0 + ii][NKq].x;
            float4 vi = *(const float4*)(vb + (size_t)i * HID + h);

            o.x = w2.x * F.x + d12.x * C.x + d01.x * aii * vi.x + d32.x * aiq * vq.x;
            o.y = w2.y * F.y + d12.y * C.y + d01.y * aii * vi.y + d32.y * aiq * vq.y;
            o.z = w2.z * F.z + d12.z * C.z + d01.z * aii * vi.z + d32.z * aiq * vq.z;
            o.w = w2.w * F.w + d12.w * C.w + d01.w * aii * vi.w + d32.w * aiq * vq.w;
        }
        *(float4*)(out + ((size_t)b * S + i) * HID + h) = o;
    }
}

// ---------------------------------------------------------------------------
extern "C" void kernel_launch(void* const* d_in, const int* in_sizes, int n_in,
                              void* d_out, int out_size)
{
    const float* q  = (const float*)d_in[0];
    const float* k  = (const float*)d_in[1];
    const float* v  = (const float*)d_in[2];
    const float* aw = (const float*)d_in[3];
    const int*   Kp = (n_in >= 6) ? (const int*)d_in[5] : nullptr;

    long rows = (long)in_sizes[0] / HID;   // B * S
    int B = 64;
    int S = (int)(rows / B);
    if (S <= 0 || (long)B * S != rows) { B = 1; S = (int)rows; }

    float* out = (float*)d_out;
    long need_with_attn = (long)B * S * HID + (long)B * S * S;
    float* attn;
    if ((long)out_size >= need_with_attn) {
        attn = out + (long)B * S * HID;
    } else {
        void* p = nullptr;
        cudaGetSymbolAddress(&p, g_attn_scratch);
        attn = (float*)p;
    }

    dim3 gA(B, (S + TI_A - 1) / TI_A);
    qk_softmax_kernel<<<gA, 256>>>(q, k, attn, S);

    dim3 gB(B, (S + TI_B - 1) / TI_B);
    out_kernel<<<gB, 256>>>(attn, v, aw, Kp, out, S);
}